// round 3
// baseline (speedup 1.0000x reference)
#include <cuda_runtime.h>

#define Bq 8
#define Nq 512
#define Fq 128
#define Hq 4
#define Uq 32
#define HU (Hq*Uq)
#define LOG2E 1.4426950408889634f

typedef unsigned long long u64;

// ---- packed f32x2 helpers (sm_103a; PTX-only, ptxas won't auto-fuse) ------
__device__ __forceinline__ u64 pk2(float lo, float hi) {
    u64 r; asm("mov.b64 %0,{%1,%2};" : "=l"(r) : "f"(lo), "f"(hi)); return r;
}
__device__ __forceinline__ void upk2(u64 v, float& lo, float& hi) {
    asm("mov.b64 {%0,%1},%2;" : "=f"(lo), "=f"(hi) : "l"(v));
}
__device__ __forceinline__ u64 add2(u64 a, u64 b) {
    u64 r; asm("add.rn.f32x2 %0,%1,%2;" : "=l"(r) : "l"(a), "l"(b)); return r;
}
__device__ __forceinline__ u64 fma2(u64 a, u64 b, u64 c) {
    u64 r; asm("fma.rn.f32x2 %0,%1,%2,%3;" : "=l"(r) : "l"(a), "l"(b), "l"(c)); return r;
}
__device__ __forceinline__ u64 relu2(u64 v) {
    float lo, hi; upk2(v, lo, hi);
    return pk2(fmaxf(lo, 0.f), fmaxf(hi, 0.f));   // 2x FMNMX, alu pipe
}
__device__ __forceinline__ float ex2f(float x) {
    float r; asm("ex2.approx.f32 %0,%1;" : "=f"(r) : "f"(x)); return r;
}

// Scratch (device globals: allocation-free)
__device__ float g_Hsrc[Bq*Hq*Nq*Uq];            // 2 MB
__device__ float g_Hdst[Bq*Hq*Nq*Uq];            // 2 MB
__device__ float g_Pl  [Bq*Hq*2*Nq*2];           // [bh][jc][i][uh]
__device__ float g_Pacc[Bq*Hq*2*Nq*2*16];        // ... [16]

// ---------------------------------------------------------------------------
// Kernel 1: projections (unchanged from R2). 128x64 tiles, 128 CTAs, 512 thr.
// ---------------------------------------------------------------------------
__global__ void __launch_bounds__(512)
proj_kernel(const float* __restrict__ inp,
            const float* __restrict__ Wsrc,
            const float* __restrict__ Wdst)
{
    extern __shared__ float sm[];
    float* sIn = sm;             // [128][132]
    float* sW  = sm + 128*132;   // [128][64]

    const int tid  = threadIdx.x;
    const int h    = blockIdx.y;
    const int row0 = blockIdx.x * 128;

    for (int t = tid; t < 128*32; t += 512) {
        int r = t >> 5, c = t & 31;
        reinterpret_cast<float4*>(sIn + r*132)[c] =
            reinterpret_cast<const float4*>(inp + (row0 + r)*Fq)[c];
    }
    for (int t = tid; t < 128*8; t += 512) {
        int k = t >> 3, c = t & 7;
        reinterpret_cast<float4*>(sW + k*64)[c] =
            reinterpret_cast<const float4*>(Wsrc + (h*Fq + k)*Uq)[c];
        reinterpret_cast<float4*>(sW + k*64 + 32)[c] =
            reinterpret_cast<const float4*>(Wdst + (h*Fq + k)*Uq)[c];
    }
    __syncthreads();

    const int tx = tid & 15;
    const int ty = tid >> 4;

    u64 acc[4][2];
    #pragma unroll
    for (int r = 0; r < 4; r++) { acc[r][0] = 0ull; acc[r][1] = 0ull; }

    for (int k0 = 0; k0 < 128; k0 += 4) {
        float rvr[4][4];
        #pragma unroll
        for (int r = 0; r < 4; r++) {
            float4 v = *reinterpret_cast<const float4*>(sIn + (ty*4 + r)*132 + k0);
            rvr[r][0] = v.x; rvr[r][1] = v.y; rvr[r][2] = v.z; rvr[r][3] = v.w;
        }
        #pragma unroll
        for (int kk = 0; kk < 4; kk++) {
            float4 cv = reinterpret_cast<const float4*>(sW + (k0 + kk)*64)[tx];
            u64 c01 = pk2(cv.x, cv.y), c23 = pk2(cv.z, cv.w);
            #pragma unroll
            for (int r = 0; r < 4; r++) {
                u64 rp = pk2(rvr[r][kk], rvr[r][kk]);
                acc[r][0] = fma2(rp, c01, acc[r][0]);
                acc[r][1] = fma2(rp, c23, acc[r][1]);
            }
        }
    }

    const int b = row0 >> 9;
    float* dstp = (tx < 8) ? g_Hsrc : g_Hdst;
    const int c4 = tx & 7;
    #pragma unroll
    for (int r = 0; r < 4; r++) {
        int n = (row0 + ty*4 + r) & (Nq - 1);
        float o0, o1, o2v, o3; upk2(acc[r][0], o0, o1); upk2(acc[r][1], o2v, o3);
        reinterpret_cast<float4*>(dstp + ((b*Hq + h)*Nq + n)*Uq)[c4] =
            make_float4(o0, o1, o2v, o3);
    }
}

// ---------------------------------------------------------------------------
// Kernel 2: attention partials. No online max (scores bounded, unshifted exp2).
// grid (4 ib, 2 jc, 32 bh), 256 threads = 128 rows x 2 u-halves. 2 CTAs/SM.
// sc[i,j] = log2e*(c_dst[j] + sum_u 0.8 a_u max(s_iu + d_ju, 0));  p = 2^sc
// ---------------------------------------------------------------------------
__global__ void __launch_bounds__(256, 2)
attn_kernel(const float* __restrict__ Av)
{
    extern __shared__ float sm[];
    float* sh_q = sm;                 // [128][32] query rows (ib block)
    float* sh_v = sm + 128*Uq;        // [256][32] value rows (jc chunk, = h_src)
    float* sh_d = sh_v + 256*Uq;      // [256][32] dst rows (jc chunk)
    float* sh_c = sh_d + 256*Uq;      // [256]

    const int tid = threadIdx.x;
    const int ib  = blockIdx.x;
    const int jc  = blockIdx.y;
    const int bh  = blockIdx.z;
    const int h   = bh & 3;

    const float* Hs = g_Hsrc + bh*Nq*Uq;
    const float* Hd = g_Hdst + bh*Nq*Uq;

    // tile loads (float4)
    for (int t = tid; t < 128*Uq/4; t += 256)
        reinterpret_cast<float4*>(sh_q)[t] =
            reinterpret_cast<const float4*>(Hs + ib*128*Uq)[t];
    for (int t = tid; t < 256*Uq/4; t += 256) {
        reinterpret_cast<float4*>(sh_v)[t] =
            reinterpret_cast<const float4*>(Hs + jc*256*Uq)[t];
        reinterpret_cast<float4*>(sh_d)[t] =
            reinterpret_cast<const float4*>(Hd + jc*256*Uq)[t];
    }
    __syncthreads();

    // c_dst for this chunk: one j per thread
    {
        const float4* dr = reinterpret_cast<const float4*>(sh_d + tid*Uq);
        const float4* ar = reinterpret_cast<const float4*>(Av + h*Uq);
        float s = 0.f;
        #pragma unroll
        for (int q = 0; q < 8; q++) {
            float4 d = dr[q], a = ar[q];
            s += d.x*a.x + d.y*a.y + d.z*a.z + d.w*a.w;
        }
        sh_c[tid] = (0.2f*LOG2E) * s;
    }
    __syncthreads();

    const int row = tid >> 1;
    const int uh  = tid & 1;          // shfl partner = lane^1
    const int ub  = uh*16;

    u64 s2[8], a2p[8], acc[8];
    {
        const float4* sp = reinterpret_cast<const float4*>(sh_q + row*Uq + ub);
        const float4* ap = reinterpret_cast<const float4*>(Av + h*Uq + ub);
        #pragma unroll
        for (int q = 0; q < 4; q++) {
            float4 v = sp[q];
            s2[2*q]   = pk2(v.x, v.y);
            s2[2*q+1] = pk2(v.z, v.w);
            float4 a = ap[q];
            const float sA = 0.8f*LOG2E;
            a2p[2*q]   = pk2(sA*a.x, sA*a.y);
            a2p[2*q+1] = pk2(sA*a.z, sA*a.w);
        }
    }
    #pragma unroll
    for (int q = 0; q < 8; q++) acc[q] = 0ull;
    float l = 0.f;

    #pragma unroll 4
    for (int j = 0; j < 256; j++) {
        const float4* dp = reinterpret_cast<const float4*>(sh_d + j*Uq + ub);
        u64 p2 = 0ull;
        #pragma unroll
        for (int q = 0; q < 4; q++) {
            float4 d = dp[q];
            p2 = fma2(a2p[2*q],   relu2(add2(s2[2*q],   pk2(d.x, d.y))), p2);
            p2 = fma2(a2p[2*q+1], relu2(add2(s2[2*q+1], pk2(d.z, d.w))), p2);
        }
        float plo, phi; upk2(p2, plo, phi);
        float ps = plo + phi;
        ps += __shfl_xor_sync(0xffffffffu, ps, 1);
        float p = ex2f(ps + sh_c[j]);
        l += p;
        u64 pp = pk2(p, p);
        const float4* vp = reinterpret_cast<const float4*>(sh_v + j*Uq + ub);
        #pragma unroll
        for (int q = 0; q < 4; q++) {
            float4 v = vp[q];
            acc[2*q]   = fma2(pp, pk2(v.x, v.y), acc[2*q]);
            acc[2*q+1] = fma2(pp, pk2(v.z, v.w), acc[2*q+1]);
        }
    }

    // store partials: rec = ((bh*2+jc)*Nq + i)*2 + uh
    const int i   = ib*128 + row;
    const int rec = ((bh*2 + jc)*Nq + i)*2 + uh;
    g_Pl[rec] = l;
    float* pa = g_Pacc + rec*16;
    #pragma unroll
    for (int q = 0; q < 4; q++) {
        float x0, x1, x2, x3;
        upk2(acc[2*q], x0, x1); upk2(acc[2*q+1], x2, x3);
        reinterpret_cast<float4*>(pa)[q] = make_float4(x0, x1, x2, x3);
    }
}

// ---------------------------------------------------------------------------
// Kernel 3: combine jc partials + normalize. 32768 threads.
// ---------------------------------------------------------------------------
__global__ void __launch_bounds__(256)
combine_kernel(float* __restrict__ out)
{
    const int idx = blockIdx.x*256 + threadIdx.x;   // (bh, i, uh)
    const int uh = idx & 1;
    const int i  = (idx >> 1) & (Nq - 1);
    const int bh = idx >> 10;
    const int b = bh >> 2, h = bh & 3;

    const int r0 = ((bh*2 + 0)*Nq + i)*2 + uh;
    const int r1 = ((bh*2 + 1)*Nq + i)*2 + uh;
    const float inv = __frcp_rn(g_Pl[r0] + g_Pl[r1]);

    const float4* A0 = reinterpret_cast<const float4*>(g_Pacc + r0*16);
    const float4* A1 = reinterpret_cast<const float4*>(g_Pacc + r1*16);
    float* op = out + (b*Nq + i)*HU + h*Uq + uh*16;
    #pragma unroll
    for (int q = 0; q < 4; q++) {
        float4 x = A0[q], y = A1[q];
        reinterpret_cast<float4*>(op)[q] =
            make_float4((x.x+y.x)*inv, (x.y+y.y)*inv,
                        (x.z+y.z)*inv, (x.w+y.w)*inv);
    }
}

// ---------------------------------------------------------------------------
extern "C" void kernel_launch(void* const* d_in, const int* in_sizes, int n_in,
                              void* d_out, int out_size)
{
    const float* inp  = (const float*)d_in[0];
    const float* Wsrc = (const float*)d_in[1];
    const float* Wdst = (const float*)d_in[2];
    const float* Av   = (const float*)d_in[3];
    float* out = (float*)d_out;

    const int PROJ_SMEM = (128*132 + 128*64) * 4;                 // 100,352 B
    const int ATTN_SMEM = (128*Uq + 2*256*Uq + 256) * 4;          //  82,944 B
    cudaFuncSetAttribute(proj_kernel,
        cudaFuncAttributeMaxDynamicSharedMemorySize, PROJ_SMEM);
    cudaFuncSetAttribute(attn_kernel,
        cudaFuncAttributeMaxDynamicSharedMemorySize, ATTN_SMEM);

    proj_kernel<<<dim3(Bq*Nq/128, Hq), 512, PROJ_SMEM>>>(inp, Wsrc, Wdst);
    attn_kernel<<<dim3(Nq/128, 2, Bq*Hq), 256, ATTN_SMEM>>>(Av);
    combine_kernel<<<Bq*Hq*Nq*2/256, 256>>>(out);
}